// round 7
// baseline (speedup 1.0000x reference)
#include <cuda_runtime.h>
#include <math.h>

// Problem constants (fixed shapes)
#define B_   4
#define C_   64
#define H_   282
#define W_   282
#define P_   12000
#define HW_  (H_ * W_)        // 79524
#define NQ_  (HW_ / 4)        // 19881 float4-quads per channel image
#define QB_  32               // quads per warp tile
#define QBLK_ ((NQ_ + QB_ - 1) / QB_)   // 622 quad-tiles per batch

#define PT_  (P_ / 32)        // 375 pillar tiles (exact)
#define CT_  (C_ / 32)        // 2  channel tiles
#define TRANS_BLOCKS_ (B_ * PT_ * CT_)            // 3000
#define IDX_BLOCKS_   ((B_ * P_ + 255) / 256)     // 188

// Scratch (device globals; zero-initialized at module load).
// g_w8: winner (p+1, 0=empty) replicated in 8 PRIVATE planes, one per
// channel-group. Each gather warp reads & resets only its own plane ->
// no sharing, no barrier, no reset kernel. 10.2 MB, L2-resident.
__device__ __align__(16) int   g_w8[8][B_ * HW_];
__device__ __align__(16) float g_tf[B_ * P_ * C_];     // feats transposed to (B, P, C)

// ---------------------------------------------------------------------------
// Kernel 1 (fused): blocks [0, 3000) transpose feats (B,C,P) -> g_tf (B,P,C);
// blocks [3000, 3188) compute per-pillar cells and atomicMax(p+1) into ALL 8
// winner planes (sequential last-update-wins == max p).
// Index math matches XLA fast-math lowering: (x + 22) * 6.25f (bit-verified).
// ---------------------------------------------------------------------------
__global__ void k_prep(const float* __restrict__ feats,
                       const float* __restrict__ pin) {
    if (blockIdx.x < TRANS_BLOCKS_) {
        __shared__ float tile[32][33];
        int bid   = blockIdx.x;
        int b     = bid / (PT_ * CT_);
        int rem   = bid - b * (PT_ * CT_);
        int ctile = rem / PT_;
        int ptile = rem - ctile * PT_;
        int tx = threadIdx.x & 31;
        int ty = threadIdx.x >> 5;

        const float* src = feats + ((size_t)b * C_ + ctile * 32) * P_ + ptile * 32;
        #pragma unroll
        for (int i = 0; i < 4; i++) {
            int cl = ty + 8 * i;
            tile[cl][tx] = src[(size_t)cl * P_ + tx];
        }
        __syncthreads();
        float* dst = g_tf + ((size_t)b * P_ + ptile * 32) * C_ + ctile * 32;
        #pragma unroll
        for (int i = 0; i < 4; i++) {
            int pl = ty + 8 * i;
            dst[(size_t)pl * C_ + tx] = tile[tx][pl];
        }
    } else {
        int i = (blockIdx.x - TRANS_BLOCKS_) * 256 + threadIdx.x;
        if (i >= B_ * P_) return;
        int b = i / P_;
        int p = i - b * P_;

        float x = pin[(b * 2 + 0) * P_ + p];
        if (x == 0.0f) return;            // invalid pillars dropped (OOB in ref)
        float y = pin[(b * 2 + 1) * P_ + p];

        int xg = (int)floorf(__fmul_rn(__fadd_rn(x, 22.0f), 6.25f));
        int yg = (int)floorf(__fmul_rn(__fadd_rn(y, 22.0f), 6.25f));
        xg = min(max(xg, 0), W_ - 1);
        yg = min(max(yg, 0), H_ - 1);
        int cell = b * HW_ + yg * W_ + xg;
        #pragma unroll
        for (int cg = 0; cg < 8; cg++)
            atomicMax(&g_w8[cg][cell], p + 1);   // one private plane per cg
    }
}

// ---------------------------------------------------------------------------
// Kernel 2: GATHER — zero barriers, zero smem. Warp = (b, cg, 32-quad tile);
// lane q owns quad (qbase+q) for channels [cg*8, cg*8+8).
//  - load own winner int4 from the PRIVATE plane g_w8[cg] (coalesced),
//    immediately reset it (sole reader -> race-free self-reset),
//  - gather 2 float4s per filled lane from the pillar's contiguous 256B
//    transposed-feature row,
//  - emit 8 coalesced float4 stores.
// Warps free-run with no phase correlation -> store pipe stays fed
// (~16 independent warps/SMSP x 14% store duty ≈ 2.2x saturation).
// ---------------------------------------------------------------------------
__global__ void __launch_bounds__(256) k_gather(float4* __restrict__ out) {
    int blk   = blockIdx.x;
    int b     = blk / QBLK_;
    int qblk  = blk - b * QBLK_;
    int qbase = qblk * QB_;
    int nq    = min(QB_, NQ_ - qbase);     // last tile per batch: 9

    int q  = threadIdx.x & 31;
    int cg = threadIdx.x >> 5;             // 0..7 = channel group (private plane)
    if (q >= nq) return;

    int4* gw4 = (int4*)g_w8[cg];
    int idx = b * NQ_ + qbase + q;
    int4 w = gw4[idx];
    gw4[idx] = make_int4(0, 0, 0, 0);      // self-reset for next call

    const float* tb = g_tf + (size_t)b * P_ * C_;
    const float4* fx = (w.x > 0) ? (const float4*)(tb + (size_t)(w.x - 1) * C_) + cg * 2 : nullptr;
    const float4* fy = (w.y > 0) ? (const float4*)(tb + (size_t)(w.y - 1) * C_) + cg * 2 : nullptr;
    const float4* fz = (w.z > 0) ? (const float4*)(tb + (size_t)(w.z - 1) * C_) + cg * 2 : nullptr;
    const float4* fw = (w.w > 0) ? (const float4*)(tb + (size_t)(w.w - 1) * C_) + cg * 2 : nullptr;

    const float4 Z = make_float4(0.f, 0.f, 0.f, 0.f);
    float4 vx0 = fx ? __ldg(fx)     : Z,  vx1 = fx ? __ldg(fx + 1) : Z;
    float4 vy0 = fy ? __ldg(fy)     : Z,  vy1 = fy ? __ldg(fy + 1) : Z;
    float4 vz0 = fz ? __ldg(fz)     : Z,  vz1 = fz ? __ldg(fz + 1) : Z;
    float4 vw0 = fw ? __ldg(fw)     : Z,  vw1 = fw ? __ldg(fw + 1) : Z;

    float4* ob = out + ((size_t)b * C_ + cg * 8) * NQ_ + qbase + q;
    ob[0 * (size_t)NQ_] = make_float4(vx0.x, vy0.x, vz0.x, vw0.x);
    ob[1 * (size_t)NQ_] = make_float4(vx0.y, vy0.y, vz0.y, vw0.y);
    ob[2 * (size_t)NQ_] = make_float4(vx0.z, vy0.z, vz0.z, vw0.z);
    ob[3 * (size_t)NQ_] = make_float4(vx0.w, vy0.w, vz0.w, vw0.w);
    ob[4 * (size_t)NQ_] = make_float4(vx1.x, vy1.x, vz1.x, vw1.x);
    ob[5 * (size_t)NQ_] = make_float4(vx1.y, vy1.y, vz1.y, vw1.y);
    ob[6 * (size_t)NQ_] = make_float4(vx1.z, vy1.z, vz1.z, vw1.z);
    ob[7 * (size_t)NQ_] = make_float4(vx1.w, vy1.w, vz1.w, vw1.w);
}

// ---------------------------------------------------------------------------
extern "C" void kernel_launch(void* const* d_in, const int* in_sizes, int n_in,
                              void* d_out, int out_size) {
    const float* pfn_input  = (const float*)d_in[0];   // (4, 2, 12000, 1)
    const float* pfn_output = (const float*)d_in[1];   // (4, 64, 12000)
    float* out = (float*)d_out;                        // (4, 64, 282, 282)

    k_prep  <<<TRANS_BLOCKS_ + IDX_BLOCKS_, 256>>>(pfn_output, pfn_input);
    k_gather<<<B_ * QBLK_,                  256>>>((float4*)out);
}

// round 8
// speedup vs baseline: 1.6564x; 1.6564x over previous
#include <cuda_runtime.h>
#include <math.h>

// Problem constants (fixed shapes)
#define B_   4
#define C_   64
#define H_   282
#define W_   282
#define P_   12000
#define HW_  (H_ * W_)        // 79524
#define NQ_  (HW_ / 4)        // 19881 float4-quads per channel image
#define QW_  16               // quads per gather warp
#define WPB_ ((NQ_ + QW_ - 1) / QW_)    // 1243 warp-tiles per batch (last: 9 quads)
#define GW_  (B_ * WPB_)                // 4972 gather warps total

#define PT_  (P_ / 32)        // 375 pillar tiles (exact)
#define CT_  (C_ / 32)        // 2  channel tiles
#define TRANS_BLOCKS_ (B_ * PT_ * CT_)            // 3000
#define IDX_BLOCKS_   ((B_ * P_ + 255) / 256)     // 188

// Scratch (device globals; zero-initialized at module load).
// g_winner: SINGLE plane, (p+1) of winning pillar, 0 = empty. Self-resetting
// inside k_gather (warp-scoped ownership) -> no reset kernel, no replication.
__device__ __align__(16) int   g_winner[B_ * HW_];
__device__ __align__(16) float g_tf[B_ * P_ * C_];     // feats transposed to (B, P, C)

// ---------------------------------------------------------------------------
// Kernel 1 (fused): blocks [0, 3000) transpose feats (B,C,P) -> g_tf (B,P,C)
// via 32x32 smem tiles; blocks [3000, 3188) compute per-pillar cells and
// atomicMax(p+1) into g_winner (sequential last-update-wins == max p).
// Index math matches XLA fast-math lowering: (x + 22) * 6.25f (bit-verified).
// ---------------------------------------------------------------------------
__global__ void k_prep(const float* __restrict__ feats,
                       const float* __restrict__ pin) {
    if (blockIdx.x < TRANS_BLOCKS_) {
        __shared__ float tile[32][33];
        int bid   = blockIdx.x;
        int b     = bid / (PT_ * CT_);
        int rem   = bid - b * (PT_ * CT_);
        int ctile = rem / PT_;
        int ptile = rem - ctile * PT_;
        int tx = threadIdx.x & 31;
        int ty = threadIdx.x >> 5;

        const float* src = feats + ((size_t)b * C_ + ctile * 32) * P_ + ptile * 32;
        #pragma unroll
        for (int i = 0; i < 4; i++) {
            int cl = ty + 8 * i;
            tile[cl][tx] = src[(size_t)cl * P_ + tx];
        }
        __syncthreads();
        float* dst = g_tf + ((size_t)b * P_ + ptile * 32) * C_ + ctile * 32;
        #pragma unroll
        for (int i = 0; i < 4; i++) {
            int pl = ty + 8 * i;
            dst[(size_t)pl * C_ + tx] = tile[tx][pl];
        }
    } else {
        int i = (blockIdx.x - TRANS_BLOCKS_) * 256 + threadIdx.x;
        if (i >= B_ * P_) return;
        int b = i / P_;
        int p = i - b * P_;

        float x = pin[(b * 2 + 0) * P_ + p];
        if (x == 0.0f) return;            // invalid pillars dropped (OOB in ref)
        float y = pin[(b * 2 + 1) * P_ + p];

        int xg = (int)floorf(__fmul_rn(__fadd_rn(x, 22.0f), 6.25f));
        int yg = (int)floorf(__fmul_rn(__fadd_rn(y, 22.0f), 6.25f));
        xg = min(max(xg, 0), W_ - 1);
        yg = min(max(yg, 0), H_ - 1);
        atomicMax(&g_winner[b * HW_ + yg * W_ + xg], p + 1);
    }
}

// ---------------------------------------------------------------------------
// Kernel 2: GATHER. Warp = (b, 16-quad tile); lane = cg*16 + qi where
// cg in {0,1} selects channels [cg*32, cg*32+32), qi in [0,16) the quad.
//  - lanes 0..15 load the tile's 16 winner int4s (one coalesced 256B read
//    of the SINGLE shared plane); __shfl_sync broadcasts quad qi's winners
//    to both cg halves; lanes 0..15 then self-reset (sole writers, shfl is
//    the intra-warp sync -> race-free; zero barriers, zero replication),
//  - per thread: 8 iterations x (up to 4 gather float4 loads from the
//    pillar's contiguous transposed-feature row + 4x4 register transpose +
//    4 coalesced float4 stores). 32 stores per winner-load (2x R5/R7
//    amortization) and 4972 warps (2x R4 parallelism).
// ---------------------------------------------------------------------------
__global__ void __launch_bounds__(256) k_gather(float4* __restrict__ out) {
    int wg = blockIdx.x * 8 + (threadIdx.x >> 5);    // global warp id
    if (wg >= GW_) return;                            // uniform per warp
    int b     = wg / WPB_;
    int tile  = wg - b * WPB_;
    int qbase = tile * QW_;
    int nq    = min(QW_, NQ_ - qbase);                // last tile per batch: 9

    int lane = threadIdx.x & 31;
    int qi   = lane & 15;
    int cg   = lane >> 4;                             // 0/1: channel half

    // ---- winner load (lanes 0..15), broadcast, self-reset ----
    int4* w4 = (int4*)g_winner;
    int gi = b * NQ_ + qbase + qi;
    int4 wl = make_int4(0, 0, 0, 0);
    if (cg == 0 && qi < nq) wl = w4[gi];

    int4 w;
    w.x = __shfl_sync(0xffffffffu, wl.x, qi);
    w.y = __shfl_sync(0xffffffffu, wl.y, qi);
    w.z = __shfl_sync(0xffffffffu, wl.z, qi);
    w.w = __shfl_sync(0xffffffffu, wl.w, qi);

    if (cg == 0 && qi < nq) w4[gi] = make_int4(0, 0, 0, 0);  // self-reset
    if (qi >= nq) return;

    // ---- gather + store: 32 channels [cg*32, cg*32+32) ----
    const float* tb = g_tf + (size_t)b * P_ * C_ + cg * 32;
    const float4* fx = (w.x > 0) ? (const float4*)(tb + (size_t)(w.x - 1) * C_) : nullptr;
    const float4* fy = (w.y > 0) ? (const float4*)(tb + (size_t)(w.y - 1) * C_) : nullptr;
    const float4* fz = (w.z > 0) ? (const float4*)(tb + (size_t)(w.z - 1) * C_) : nullptr;
    const float4* fw = (w.w > 0) ? (const float4*)(tb + (size_t)(w.w - 1) * C_) : nullptr;

    const float4 Z = make_float4(0.f, 0.f, 0.f, 0.f);
    float4* ob = out + ((size_t)b * C_ + cg * 32) * NQ_ + qbase + qi;

    #pragma unroll
    for (int gg = 0; gg < 8; gg++) {     // 4 channels per iteration
        float4 vx = fx ? __ldg(fx + gg) : Z;
        float4 vy = fy ? __ldg(fy + gg) : Z;
        float4 vz = fz ? __ldg(fz + gg) : Z;
        float4 vw = fw ? __ldg(fw + gg) : Z;

        ob[(size_t)(gg * 4 + 0) * NQ_] = make_float4(vx.x, vy.x, vz.x, vw.x);
        ob[(size_t)(gg * 4 + 1) * NQ_] = make_float4(vx.y, vy.y, vz.y, vw.y);
        ob[(size_t)(gg * 4 + 2) * NQ_] = make_float4(vx.z, vy.z, vz.z, vw.z);
        ob[(size_t)(gg * 4 + 3) * NQ_] = make_float4(vx.w, vy.w, vz.w, vw.w);
    }
}

// ---------------------------------------------------------------------------
extern "C" void kernel_launch(void* const* d_in, const int* in_sizes, int n_in,
                              void* d_out, int out_size) {
    const float* pfn_input  = (const float*)d_in[0];   // (4, 2, 12000, 1)
    const float* pfn_output = (const float*)d_in[1];   // (4, 64, 12000)
    float* out = (float*)d_out;                        // (4, 64, 282, 282)

    k_prep  <<<TRANS_BLOCKS_ + IDX_BLOCKS_, 256>>>(pfn_output, pfn_input);
    k_gather<<<(GW_ + 7) / 8,               256>>>((float4*)out);
}